// round 9
// baseline (speedup 1.0000x reference)
#include <cuda_runtime.h>
#include <cuda_bf16.h>
#include <cstdint>

#define B_      1024
#define L_      50
#define K_      20
#define D_      64
#define NITEMS  100000
#define NUSERS  10000
#define ALPHA   0.2f

#define NT_PAD   12512              // n8-tiles padded to multiple of 16
#define NGROUPS  (NT_PAD / 16)      // 782 groups of 128 cols
#define STRIPS   8
#define SLOTS    18                 // 144 CTAs, one wave
#define NCTAS    (STRIPS * SLOTS)   // 144

#define RECUR_CTAS 64
#define NPAIRS     (NT_PAD / 4)     // 3128 pairs of 16-row groups

__device__ float g_pu[B_ * D_];
// B fragments: [nt][j(4)][lane(32)] uint4 (k-step pair 2j,2j+1), column-paired
__device__ uint4 g_bfrag[NT_PAD * 4 * 32];     // 25.6 MB
__device__ unsigned g_bar = 0;                 // monotonic ticket barrier

__device__ __forceinline__ uint32_t f2tf32(float x) {
    uint32_t u;
    asm("cvt.rn.tf32.f32 %0, %1;" : "=r"(u) : "f"(x));
    return u;
}
__device__ __forceinline__ uint32_t smem_u32(const void* p) {
    uint32_t a;
    asm("{ .reg .u64 t; cvta.to.shared.u64 t, %1; cvt.u32.u64 %0, t; }"
        : "=r"(a) : "l"(p));
    return a;
}
__device__ __forceinline__ void cp_async16(uint32_t dst, const void* src) {
    asm volatile("cp.async.cg.shared.global [%0], [%1], 16;"
                 :: "r"(dst), "l"(src) : "memory");
}
#define CP_COMMIT() asm volatile("cp.async.commit_group;" ::: "memory")
#define CP_WAIT(n)  asm volatile("cp.async.wait_group %0;" :: "n"(n) : "memory")

__device__ __forceinline__ void mma_tf32(float& c0, float& c1, float& c2, float& c3,
                                         uint32_t a0, uint32_t a1, uint32_t a2, uint32_t a3,
                                         uint32_t b0, uint32_t b1) {
    asm volatile("mma.sync.aligned.m16n8k8.row.col.f32.tf32.tf32.f32 "
                 "{%0,%1,%2,%3}, {%4,%5,%6,%7}, {%8,%9}, {%0,%1,%2,%3};"
                 : "+f"(c0), "+f"(c1), "+f"(c2), "+f"(c3)
                 : "r"(a0), "r"(a1), "r"(a2), "r"(a3), "r"(b0), "r"(b1));
}

__device__ __forceinline__ float tree_sum20(const float* s) {
    float t1[10];
#pragma unroll
    for (int i = 0; i < 10; i++) t1[i] = s[2 * i] + s[2 * i + 1];
    float t2[5];
#pragma unroll
    for (int i = 0; i < 5; i++) t2[i] = t1[2 * i] + t1[2 * i + 1];
    return ((t2[0] + t2[1]) + (t2[2] + t2[3])) + t2[4];
}

#define TILE_U4   2048                       // uint4 per 128-col B group
#define GEMM_SMEM_BYTES (3 * TILE_U4 * 16)   // 96 KB

// ---------------------------------------------------------------------------
// Phase-1 helper: transform one PAIR of 16-row groups (32 item rows) into
// fragment layout.  All 512 threads participate; sstage = 32*68 floats.
// ---------------------------------------------------------------------------
__device__ __forceinline__ void bfrag_pair(int p, const float* __restrict__ item,
                                           float* sstage)
{
    const int tid = threadIdx.x;
    __syncthreads();            // protect previous iteration's reads
    {
        int row = tid >> 4;                 // 0..31
        int f4  = tid & 15;
        int n   = p * 32 + row;
        float4 v = make_float4(0.f, 0.f, 0.f, 0.f);
        if (n < NITEMS)
            v = *((const float4*)(item + (size_t)n * 64) + f4);
        *(float4*)&sstage[row * 68 + f4 * 4] = v;
    }
    __syncthreads();
    {
        const int lane = tid & 31;
        const int j    = (tid >> 5) & 3;
        const int par  = (tid >> 7) & 1;
        const int gl   = tid >> 8;          // which group of the pair
        const int w    = lane >> 2;
        const int t    = lane & 3;
        const int nl   = ((w & 1) ? (2 * w - 1 + 2 * par) : (2 * w + 2 * par)) + gl * 16;
        uint4 v;
        v.x = f2tf32(sstage[nl * 68 + (j * 4 + 0) * 4 + t]);
        v.y = f2tf32(sstage[nl * 68 + (j * 4 + 1) * 4 + t]);
        v.z = f2tf32(sstage[nl * 68 + (j * 4 + 2) * 4 + t]);
        v.w = f2tf32(sstage[nl * 68 + (j * 4 + 3) * 4 + t]);
        g_bfrag[(size_t)(p * 2 + gl) * 256 + (tid & 255)] = v;
    }
}

// ===========================================================================
// Single fused persistent kernel.
// Phase 1: CTAs [0,64) recurrence (16 rows each) then bfrag tail;
//          CTAs [64,144) bfrag transform.
// Ticket barrier (all 144 CTAs co-resident: 96KB smem -> 1 CTA/SM).
// Phase 2: persistent GEMM (R7 config: A in regs, 3-stage cp.async ring).
// ===========================================================================
__global__ void __launch_bounds__(512, 1)
fused_kernel(const float* __restrict__ item,
             const float* __restrict__ user,
             const float* __restrict__ mem_init,
             const int*   __restrict__ user_id,
             const int*   __restrict__ seq,
             const int*   __restrict__ seq_len,
             float* __restrict__ C)
{
    extern __shared__ uint4 smem[];          // 96KB
    float* const sstage = (float*)smem;      // phase-1 scratch (8.7KB)
    int*   const sseq   = (int*)smem;        // recurrence seq stage (3.2KB)

    const int tid  = threadIdx.x;
    const int wid  = tid >> 5;
    const int lane = tid & 31;
    const int cta  = blockIdx.x;

    // ======================= PHASE 1 =======================
    if (cta < RECUR_CTAS) {
        // ---- recurrence: 16 warps = 16 batch rows ----
        for (int i = tid; i < 16 * L_; i += 512)
            sseq[i] = seq[cta * 16 * L_ + i];
        __syncthreads();

        const int b = cta * 16 + wid;
        float m0[K_], m1[K_];
        const float* mi = mem_init + (size_t)b * K_ * D_;
#pragma unroll
        for (int k = 0; k < K_; k++) {
            m0[k] = mi[k * D_ + lane];
            m1[k] = mi[k * D_ + lane + 32];
        }

        const int T = seq_len[b];
        const int* sq = sseq + wid * L_;
        int last_idx = sq[L_ - 1];           // read before smem is reused

        for (int t0 = 0; t0 < T; t0 += 8) {
            int nt = min(8, T - t0);
            float e0[8], e1[8];
#pragma unroll
            for (int i = 0; i < 8; i++) {
                if (i < nt) {
                    int idx = sq[t0 + i];
                    e0[i] = __ldg(item + (size_t)idx * D_ + lane);
                    e1[i] = __ldg(item + (size_t)idx * D_ + lane + 32);
                }
            }
#pragma unroll
            for (int i = 0; i < 8; i++) {
                if (i >= nt) break;
                float s[K_];
#pragma unroll
                for (int k = 0; k < K_; k++) {
                    float p = fmaf(m0[k], e0[i], m1[k] * e1[i]);
#pragma unroll
                    for (int off = 16; off > 0; off >>= 1)
                        p += __shfl_xor_sync(0xffffffffu, p, off);
                    s[k] = p;
                }
#pragma unroll
                for (int k = 0; k < K_; k++) s[k] = __expf(s[k]);
                float inv = __fdividef(1.f, tree_sum20(s));
                float er0 = __fdividef(1.f, 1.f + __expf(-e0[i]));
                float er1 = __fdividef(1.f, 1.f + __expf(-e1[i]));
                float ex0 = __expf(2.f * e0[i]);
                float ex1 = __expf(2.f * e1[i]);
                float ad0 = __fdividef(ex0 - 1.f, ex0 + 1.f);
                float ad1 = __fdividef(ex1 - 1.f, ex1 + 1.f);
#pragma unroll
                for (int k = 0; k < K_; k++) {
                    float z = s[k] * inv;
                    m0[k] = m0[k] * (1.f - z * er0) + z * ad0;
                    m1[k] = m1[k] * (1.f - z * er1) + z * ad1;
                }
            }
        }

        float l0 = __ldg(item + (size_t)last_idx * D_ + lane);
        float l1 = __ldg(item + (size_t)last_idx * D_ + lane + 32);
        float s[K_];
#pragma unroll
        for (int k = 0; k < K_; k++) {
            float p = fmaf(m0[k], l0, m1[k] * l1);
#pragma unroll
            for (int off = 16; off > 0; off >>= 1)
                p += __shfl_xor_sync(0xffffffffu, p, off);
            s[k] = __expf(p);
        }
        float inv = __fdividef(1.f, tree_sum20(s));
        float p0 = 0.f, p1 = 0.f;
#pragma unroll
        for (int k = 0; k < K_; k++) {
            float z = s[k] * inv;
            p0 = fmaf(z, m0[k], p0);
            p1 = fmaf(z, m1[k], p1);
        }
        int uid = user_id[b];
        g_pu[b * D_ + lane]      = user[(size_t)uid * D_ + lane]      + ALPHA * p0;
        g_pu[b * D_ + lane + 32] = user[(size_t)uid * D_ + lane + 32] + ALPHA * p1;

        // ---- bfrag tail: pairs [2560 + cta*9, +9) ----
        int pbeg = 2560 + cta * 9;
        int pend = min(pbeg + 9, NPAIRS);
        for (int p = pbeg; p < pend; p++)
            bfrag_pair(p, item, sstage);
    } else {
        // ---- bfrag main: pairs [i*32, +32) ----
        int i = cta - RECUR_CTAS;
        int pbeg = i * 32;
        int pend = min(pbeg + 32, 2560);
        for (int p = pbeg; p < pend; p++)
            bfrag_pair(p, item, sstage);
    }

    // ======================= BARRIER =======================
    __threadfence();
    __syncthreads();
    if (tid == 0) {
        unsigned ticket = atomicAdd(&g_bar, 1u);
        unsigned target = (ticket / NCTAS + 1u) * NCTAS;
        while (*(volatile unsigned*)&g_bar < target) { }
    }
    __syncthreads();
    __threadfence();

    // ======================= PHASE 2: GEMM =======================
    const uint32_t sBb = smem_u32(smem);
    const int wm   = wid >> 2;               // 0..3 (32 rows)
    const int wn   = wid & 3;                // 0..3 (32 cols)
    const int g    = lane >> 2;
    const int t    = lane & 3;

    const int strip = cta & 7;
    const int slot  = cta >> 3;

    // A: convert this warp's 32-row slice of pu into registers
    uint4 a[2][8];
    {
        const float* pu = g_pu + (size_t)(strip * 128 + wm * 32) * 64;
#pragma unroll
        for (int mi = 0; mi < 2; mi++) {
            int r0 = mi * 16 + g;
#pragma unroll
            for (int ks = 0; ks < 8; ks++) {
                int k0 = ks * 8 + t;
                a[mi][ks].x = f2tf32(pu[r0 * 64 + k0]);
                a[mi][ks].y = f2tf32(pu[(r0 + 8) * 64 + k0]);
                a[mi][ks].z = f2tf32(pu[r0 * 64 + k0 + 4]);
                a[mi][ks].w = f2tf32(pu[(r0 + 8) * 64 + k0 + 4]);
            }
        }
    }

    const int row_base = strip * 128 + wm * 32;

    // prologue: stage groups for iter 0,1 into ring buffers 0,1
#pragma unroll
    for (int pf = 0; pf < 2; pf++) {
        int grp = slot + pf * SLOTS;
        if (grp < NGROUPS) {
            const uint4* src = g_bfrag + (size_t)grp * TILE_U4 + tid;
            uint32_t dst = sBb + (uint32_t)(pf * TILE_U4 + tid) * 16u;
#pragma unroll
            for (int r = 0; r < 4; r++)
                cp_async16(dst + r * 512 * 16, src + r * 512);
        }
        CP_COMMIT();
    }

    int iter = 0;
    for (int grp = slot; grp < NGROUPS; grp += SLOTS, iter++) {
        const int buf = iter - (iter / 3) * 3;
        CP_WAIT(1);
        __syncthreads();

        // prefetch iter+2 into the just-freed buffer
        {
            int nxt = grp + 2 * SLOTS;
            if (nxt < NGROUPS) {
                const int pbuf = (buf + 2 >= 3) ? buf - 1 : buf + 2;
                const uint4* src = g_bfrag + (size_t)nxt * TILE_U4 + tid;
                uint32_t dst = sBb + (uint32_t)(pbuf * TILE_U4 + tid) * 16u;
#pragma unroll
                for (int r = 0; r < 4; r++)
                    cp_async16(dst + r * 512 * 16, src + r * 512);
            }
            CP_COMMIT();
        }

        float acc[2][2][2][4];
#pragma unroll
        for (int i = 0; i < 2; i++)
#pragma unroll
            for (int p = 0; p < 2; p++)
#pragma unroll
                for (int q = 0; q < 2; q++)
#pragma unroll
                    for (int r = 0; r < 4; r++) acc[i][p][q][r] = 0.f;

        const uint4* Bs = smem + buf * TILE_U4;
#pragma unroll
        for (int j = 0; j < 4; j++) {
            uint4 b[2][2];
#pragma unroll
            for (int p = 0; p < 2; p++)
#pragma unroll
                for (int q = 0; q < 2; q++)
                    b[p][q] = Bs[((wn * 4 + p * 2 + q) * 4 + j) * 32 + lane];
#pragma unroll
            for (int s = 0; s < 2; s++) {
                const int ks = 2 * j + s;
#pragma unroll
                for (int mi = 0; mi < 2; mi++)
#pragma unroll
                    for (int p = 0; p < 2; p++)
#pragma unroll
                        for (int q = 0; q < 2; q++) {
                            uint32_t b0 = (s == 0) ? b[p][q].x : b[p][q].z;
                            uint32_t b1 = (s == 0) ? b[p][q].y : b[p][q].w;
                            mma_tf32(acc[mi][p][q][0], acc[mi][p][q][1],
                                     acc[mi][p][q][2], acc[mi][p][q][3],
                                     a[mi][ks].x, a[mi][ks].y, a[mi][ks].z, a[mi][ks].w,
                                     b0, b1);
                        }
            }
        }

        // epilogue: STG.128 streaming stores
#pragma unroll
        for (int mi = 0; mi < 2; mi++) {
            int row0 = row_base + mi * 16 + g;
#pragma unroll
            for (int p = 0; p < 2; p++) {
                int base16 = grp * 128 + wn * 32 + p * 16;
                if (base16 < NITEMS) {       // NITEMS % 16 == 0
                    int col = base16 + 4 * t;
                    __stcs((float4*)(C + (size_t)row0 * NITEMS + col),
                           make_float4(acc[mi][p][0][0], acc[mi][p][0][1],
                                       acc[mi][p][1][0], acc[mi][p][1][1]));
                    __stcs((float4*)(C + (size_t)(row0 + 8) * NITEMS + col),
                           make_float4(acc[mi][p][0][2], acc[mi][p][0][3],
                                       acc[mi][p][1][2], acc[mi][p][1][3]));
                }
            }
        }
    }
}

// ===========================================================================
extern "C" void kernel_launch(void* const* d_in, const int* in_sizes, int n_in,
                              void* d_out, int out_size)
{
    const float* item_table  = (const float*)d_in[0];
    const float* user_table  = (const float*)d_in[1];
    const float* memory_init = (const float*)d_in[2];
    const int*   user_id     = (const int*)d_in[3];
    const int*   seq         = (const int*)d_in[4];
    const int*   seq_length  = (const int*)d_in[5];
    float*       scores      = (float*)d_out;

    cudaFuncSetAttribute(fused_kernel,
                         cudaFuncAttributeMaxDynamicSharedMemorySize,
                         GEMM_SMEM_BYTES);

    fused_kernel<<<NCTAS, 512, GEMM_SMEM_BYTES>>>(
        item_table, user_table, memory_init, user_id, seq, seq_length, scores);
}

// round 10
// speedup vs baseline: 1.0851x; 1.0851x over previous
#include <cuda_runtime.h>
#include <cuda_bf16.h>
#include <cstdint>

#define B_      1024
#define L_      50
#define K_      20
#define D_      64
#define NITEMS  100000
#define NUSERS  10000
#define ALPHA   0.2f

#define NT_PAD   12512              // n8-tiles padded to multiple of 16
#define NGROUPS  (NT_PAD / 16)      // 782 groups of 128 cols
#define STRIPS   8
#define SLOTS    18                 // 144 CTAs, one wave

__device__ float g_pu[B_ * D_];
// B fragments: [nt][j(4)][lane(32)] uint4 (k-step pair 2j,2j+1), column-paired
__device__ uint4 g_bfrag[NT_PAD * 4 * 32];     // 25.6 MB

__device__ __forceinline__ uint32_t f2tf32(float x) {
    uint32_t u;
    asm("cvt.rn.tf32.f32 %0, %1;" : "=r"(u) : "f"(x));
    return u;
}
__device__ __forceinline__ uint32_t smem_u32(const void* p) {
    uint32_t a;
    asm("{ .reg .u64 t; cvta.to.shared.u64 t, %1; cvt.u32.u64 %0, t; }"
        : "=r"(a) : "l"(p));
    return a;
}

#define MBAR_INIT(mbar, cnt) \
    asm volatile("mbarrier.init.shared.b64 [%0], %1;" \
                 :: "r"((uint32_t)(mbar)), "r"((uint32_t)(cnt)) : "memory")
#define MBAR_EXPECT_TX(mbar, bytes) \
    asm volatile("mbarrier.arrive.expect_tx.shared.b64 _, [%0], %1;" \
                 :: "r"((uint32_t)(mbar)), "r"((uint32_t)(bytes)) : "memory")
#define MBAR_WAIT(mbar, ph) do {                                              \
    uint32_t _m = (uint32_t)(mbar); uint32_t _p = (uint32_t)(ph);             \
    asm volatile(                                                             \
        "{\n\t.reg .pred P1;\n\t"                                             \
        "WAIT_LOOP_%=:\n\t"                                                   \
        "mbarrier.try_wait.parity.acquire.cta.shared::cta.b64 P1, [%0], %1, 0x989680;\n\t" \
        "@P1 bra.uni WAIT_DONE_%=;\n\t"                                       \
        "bra.uni WAIT_LOOP_%=;\n\t"                                           \
        "WAIT_DONE_%=:\n\t}"                                                  \
        :: "r"(_m), "r"(_p) : "memory");                                      \
} while (0)
// one-instruction 32KB copy: global -> shared, completion via mbarrier tx
#define BULK_COPY(dst_smem, src_gmem, bytes, mbar) \
    asm volatile("cp.async.bulk.shared::cluster.global.mbarrier::complete_tx::bytes " \
                 "[%0], [%1], %2, [%3];" \
                 :: "r"((uint32_t)(dst_smem)), "l"(src_gmem), \
                    "r"((uint32_t)(bytes)), "r"((uint32_t)(mbar)) : "memory")

__device__ __forceinline__ void mma_tf32(float& c0, float& c1, float& c2, float& c3,
                                         uint32_t a0, uint32_t a1, uint32_t a2, uint32_t a3,
                                         uint32_t b0, uint32_t b1) {
    asm volatile("mma.sync.aligned.m16n8k8.row.col.f32.tf32.tf32.f32 "
                 "{%0,%1,%2,%3}, {%4,%5,%6,%7}, {%8,%9}, {%0,%1,%2,%3};"
                 : "+f"(c0), "+f"(c1), "+f"(c2), "+f"(c3)
                 : "r"(a0), "r"(a1), "r"(a2), "r"(a3), "r"(b0), "r"(b1));
}

__device__ __forceinline__ float tree_sum20(const float* s) {
    float t1[10];
#pragma unroll
    for (int i = 0; i < 10; i++) t1[i] = s[2 * i] + s[2 * i + 1];
    float t2[5];
#pragma unroll
    for (int i = 0; i < 5; i++) t2[i] = t1[2 * i] + t1[2 * i + 1];
    return ((t2[0] + t2[1]) + (t2[2] + t2[3])) + t2[4];
}

// ===========================================================================
// Fused prep kernel (256 threads/block)  [R8 structure — best measured]
//   blocks [0,128):  recurrence for 8 batch rows -> g_pu
//   blocks [128,..): B fragment transform, smem-staged (vectorized LDG)
// ===========================================================================
#define RECUR_BLOCKS 128
#define BFRAG_BLOCKS (NT_PAD / 2)           // 6256

__global__ void __launch_bounds__(256)
prep_kernel(const float* __restrict__ item,
            const float* __restrict__ user,
            const float* __restrict__ mem_init,
            const int*   __restrict__ user_id,
            const int*   __restrict__ seq,
            const int*   __restrict__ seq_len)
{
    __shared__ float sstage[16 * 68];
    __shared__ int   sseq[8 * L_];
    const int tid = threadIdx.x;

    if (blockIdx.x >= RECUR_BLOCKS) {
        const int ntg = blockIdx.x - RECUR_BLOCKS;        // 16-row group
        {
            int row = tid >> 4;
            int f4  = tid & 15;
            int n   = ntg * 16 + row;
            float4 v = make_float4(0.f, 0.f, 0.f, 0.f);
            if (n < NITEMS)
                v = *((const float4*)(item + (size_t)n * 64) + f4);
            *(float4*)&sstage[row * 68 + f4 * 4] = v;
        }
        __syncthreads();

        const int lane = tid & 31;
        const int j    = (tid >> 5) & 3;
        const int par  = tid >> 7;
        const int w    = lane >> 2;
        const int t    = lane & 3;
        const int nl = (w & 1) ? (2 * w - 1 + 2 * par) : (2 * w + 2 * par);
        uint4 v;
        v.x = f2tf32(sstage[nl * 68 + (j * 4 + 0) * 4 + t]);
        v.y = f2tf32(sstage[nl * 68 + (j * 4 + 1) * 4 + t]);
        v.z = f2tf32(sstage[nl * 68 + (j * 4 + 2) * 4 + t]);
        v.w = f2tf32(sstage[nl * 68 + (j * 4 + 3) * 4 + t]);
        g_bfrag[(size_t)ntg * 256 + tid] = v;
        return;
    }

    // ---------------- recurrence: 8 warps = 8 batch rows ----------------
    const int wid  = tid >> 5;
    const int lane = tid & 31;
    const int b    = blockIdx.x * 8 + wid;

    for (int i = tid; i < 8 * L_; i += 256)
        sseq[i] = seq[blockIdx.x * 8 * L_ + i];
    __syncthreads();

    float m0[K_], m1[K_];
    const float* mi = mem_init + (size_t)b * K_ * D_;
#pragma unroll
    for (int k = 0; k < K_; k++) {
        m0[k] = mi[k * D_ + lane];
        m1[k] = mi[k * D_ + lane + 32];
    }

    const int T = seq_len[b];
    const int* sq = sseq + wid * L_;

    for (int t0 = 0; t0 < T; t0 += 8) {
        int nt = min(8, T - t0);
        float e0[8], e1[8];
#pragma unroll
        for (int i = 0; i < 8; i++) {
            if (i < nt) {
                int idx = sq[t0 + i];
                e0[i] = __ldg(item + (size_t)idx * D_ + lane);
                e1[i] = __ldg(item + (size_t)idx * D_ + lane + 32);
            }
        }
#pragma unroll
        for (int i = 0; i < 8; i++) {
            if (i >= nt) break;
            float s[K_];
#pragma unroll
            for (int k = 0; k < K_; k++) {
                float p = fmaf(m0[k], e0[i], m1[k] * e1[i]);
#pragma unroll
                for (int off = 16; off > 0; off >>= 1)
                    p += __shfl_xor_sync(0xffffffffu, p, off);
                s[k] = p;
            }
#pragma unroll
            for (int k = 0; k < K_; k++) s[k] = __expf(s[k]);
            float inv = __fdividef(1.f, tree_sum20(s));
            float er0 = __fdividef(1.f, 1.f + __expf(-e0[i]));
            float er1 = __fdividef(1.f, 1.f + __expf(-e1[i]));
            float ex0 = __expf(2.f * e0[i]);
            float ex1 = __expf(2.f * e1[i]);
            float ad0 = __fdividef(ex0 - 1.f, ex0 + 1.f);
            float ad1 = __fdividef(ex1 - 1.f, ex1 + 1.f);
#pragma unroll
            for (int k = 0; k < K_; k++) {
                float z = s[k] * inv;
                m0[k] = m0[k] * (1.f - z * er0) + z * ad0;
                m1[k] = m1[k] * (1.f - z * er1) + z * ad1;
            }
        }
    }

    int lidx = sq[L_ - 1];
    float l0 = __ldg(item + (size_t)lidx * D_ + lane);
    float l1 = __ldg(item + (size_t)lidx * D_ + lane + 32);

    float s[K_];
#pragma unroll
    for (int k = 0; k < K_; k++) {
        float p = fmaf(m0[k], l0, m1[k] * l1);
#pragma unroll
        for (int off = 16; off > 0; off >>= 1)
            p += __shfl_xor_sync(0xffffffffu, p, off);
        s[k] = __expf(p);
    }
    float inv = __fdividef(1.f, tree_sum20(s));

    float p0 = 0.f, p1 = 0.f;
#pragma unroll
    for (int k = 0; k < K_; k++) {
        float z = s[k] * inv;
        p0 = fmaf(z, m0[k], p0);
        p1 = fmaf(z, m1[k], p1);
    }

    int uid = user_id[b];
    g_pu[b * D_ + lane]      = user[(size_t)uid * D_ + lane]      + ALPHA * p0;
    g_pu[b * D_ + lane + 32] = user[(size_t)uid * D_ + lane + 32] + ALPHA * p1;
}

// ===========================================================================
// Persistent GEMM: 144 CTAs (8 strips x 18 slots), 512 thr = 16 warps (4Mx4N).
// A in registers.  B: 3-stage ring filled by cp.async.bulk (ONE instruction
// per 32KB group, mbarrier completion) -- removes the LDGSTS issue floor.
// Epilogue: STG.128 streaming store burst (R7 config).
// ===========================================================================
#define TILE_BYTES 32768
#define TILE_U4    2048
#define GEMM_SMEM_BYTES (1024 + 3 * TILE_BYTES)   // header + ring = 99328

__global__ void __launch_bounds__(512, 1)
gemm_persist(float* __restrict__ C)
{
    extern __shared__ char smem[];
    const uint32_t sbase = smem_u32(smem);
    const uint32_t mbar0 = sbase;                    // 3 mbarriers @ +0,+8,+16
    const uint32_t bufs  = sbase + 1024;
    uint4* const sB = (uint4*)(smem + 1024);

    const int tid  = threadIdx.x;
    const int wid  = tid >> 5;
    const int lane = tid & 31;
    const int wm   = wid >> 2;
    const int wn   = wid & 3;
    const int g    = lane >> 2;
    const int t    = lane & 3;

    const int strip = blockIdx.x & 7;
    const int slot  = blockIdx.x >> 3;

    // ---- A: convert this warp's 32-row slice of pu into registers ----
    uint4 a[2][8];
    {
        const float* pu = g_pu + (size_t)(strip * 128 + wm * 32) * 64;
#pragma unroll
        for (int mi = 0; mi < 2; mi++) {
            int r0 = mi * 16 + g;
#pragma unroll
            for (int ks = 0; ks < 8; ks++) {
                int k0 = ks * 8 + t;
                a[mi][ks].x = f2tf32(pu[r0 * 64 + k0]);
                a[mi][ks].y = f2tf32(pu[(r0 + 8) * 64 + k0]);
                a[mi][ks].z = f2tf32(pu[r0 * 64 + k0 + 4]);
                a[mi][ks].w = f2tf32(pu[(r0 + 8) * 64 + k0 + 4]);
            }
        }
    }

    const int row_base = strip * 128 + wm * 32;

    // ---- init mbarriers, prologue fills for iter 0,1 ----
    if (tid == 0) {
        MBAR_INIT(mbar0 + 0,  1);
        MBAR_INIT(mbar0 + 8,  1);
        MBAR_INIT(mbar0 + 16, 1);
    }
    __syncthreads();
    if (tid == 0) {
#pragma unroll
        for (int pf = 0; pf < 2; pf++) {
            int grp = slot + pf * SLOTS;          // always < NGROUPS (max 35)
            MBAR_EXPECT_TX(mbar0 + pf * 8, TILE_BYTES);
            BULK_COPY(bufs + pf * TILE_BYTES, g_bfrag + (size_t)grp * TILE_U4,
                      TILE_BYTES, mbar0 + pf * 8);
        }
    }

    int iter = 0;
    for (int grp = slot; grp < NGROUPS; grp += SLOTS, iter++) {
        const int fill = iter / 3;
        const int buf  = iter - fill * 3;
        MBAR_WAIT(mbar0 + buf * 8, fill & 1);
        __syncthreads();     // all warps done with buffer (iter-1)%3

        // prefetch iter+2 into the just-freed buffer
        if (tid == 0) {
            int nxt = grp + 2 * SLOTS;
            if (nxt < NGROUPS) {
                const int pbuf = (buf + 2 >= 3) ? buf - 1 : buf + 2;
                MBAR_EXPECT_TX(mbar0 + pbuf * 8, TILE_BYTES);
                BULK_COPY(bufs + pbuf * TILE_BYTES,
                          g_bfrag + (size_t)nxt * TILE_U4,
                          TILE_BYTES, mbar0 + pbuf * 8);
            }
        }

        float acc[2][2][2][4];
#pragma unroll
        for (int i = 0; i < 2; i++)
#pragma unroll
            for (int p = 0; p < 2; p++)
#pragma unroll
                for (int q = 0; q < 2; q++)
#pragma unroll
                    for (int r = 0; r < 4; r++) acc[i][p][q][r] = 0.f;

        const uint4* Bs = sB + buf * TILE_U4;
#pragma unroll
        for (int j = 0; j < 4; j++) {
            uint4 b[2][2];
#pragma unroll
            for (int p = 0; p < 2; p++)
#pragma unroll
                for (int q = 0; q < 2; q++)
                    b[p][q] = Bs[((wn * 4 + p * 2 + q) * 4 + j) * 32 + lane];
#pragma unroll
            for (int s = 0; s < 2; s++) {
                const int ks = 2 * j + s;
#pragma unroll
                for (int mi = 0; mi < 2; mi++)
#pragma unroll
                    for (int p = 0; p < 2; p++)
#pragma unroll
                        for (int q = 0; q < 2; q++) {
                            uint32_t b0 = (s == 0) ? b[p][q].x : b[p][q].z;
                            uint32_t b1 = (s == 0) ? b[p][q].y : b[p][q].w;
                            mma_tf32(acc[mi][p][q][0], acc[mi][p][q][1],
                                     acc[mi][p][q][2], acc[mi][p][q][3],
                                     a[mi][ks].x, a[mi][ks].y, a[mi][ks].z, a[mi][ks].w,
                                     b0, b1);
                        }
            }
        }

        // ---- epilogue: STG.128 streaming store burst ----
#pragma unroll
        for (int mi = 0; mi < 2; mi++) {
            int row0 = row_base + mi * 16 + g;
#pragma unroll
            for (int p = 0; p < 2; p++) {
                int base16 = grp * 128 + wn * 32 + p * 16;
                if (base16 < NITEMS) {       // NITEMS % 16 == 0
                    int col = base16 + 4 * t;
                    __stcs((float4*)(C + (size_t)row0 * NITEMS + col),
                           make_float4(acc[mi][p][0][0], acc[mi][p][0][1],
                                       acc[mi][p][1][0], acc[mi][p][1][1]));
                    __stcs((float4*)(C + (size_t)(row0 + 8) * NITEMS + col),
                           make_float4(acc[mi][p][0][2], acc[mi][p][0][3],
                                       acc[mi][p][1][2], acc[mi][p][1][3]));
                }
            }
        }
    }
}

// ===========================================================================
extern "C" void kernel_launch(void* const* d_in, const int* in_sizes, int n_in,
                              void* d_out, int out_size)
{
    const float* item_table  = (const float*)d_in[0];
    const float* user_table  = (const float*)d_in[1];
    const float* memory_init = (const float*)d_in[2];
    const int*   user_id     = (const int*)d_in[3];
    const int*   seq         = (const int*)d_in[4];
    const int*   seq_length  = (const int*)d_in[5];
    float*       scores      = (float*)d_out;

    cudaFuncSetAttribute(gemm_persist,
                         cudaFuncAttributeMaxDynamicSharedMemorySize,
                         GEMM_SMEM_BYTES);

    prep_kernel<<<RECUR_BLOCKS + BFRAG_BLOCKS, 256>>>(
        item_table, user_table, memory_init, user_id, seq, seq_length);

    gemm_persist<<<STRIPS * SLOTS, 512, GEMM_SMEM_BYTES>>>(scores);
}